// round 4
// baseline (speedup 1.0000x reference)
#include <cuda_runtime.h>

#define BB 32
#define NN 1024
#define CC 1024
#define HH 16
#define HD 64
#define AA 49
#define LOG2E 1.4426950408889634f

__device__ __forceinline__ float fast_exp2(float x) {
    float y;
    asm("ex2.approx.ftz.f32 %0, %1;" : "=f"(y) : "f"(x));
    return y;
}

// ---------------- scratch (__device__ globals; no dynamic alloc) ----------------
__device__ float  g_Aq[4*1024];     // [w_vel@wq ; b_vel@wq + bq]
__device__ float  g_Ak[4*1024];
__device__ float  g_Av[4*1024];
__device__ float  g_M1[16*16];      // per-head 4x4 bilinear (scaled by log2 e)
__device__ float  g_M2[16*16];
__device__ float  g_G [16*4*3];     // per-head Av_h @ wproj_h
__device__ float  g_T4[4*3*3];      // conv+proj fused tensor (row 3 = bias taps)
__device__ float  g_Db[3];          // dwc_b @ wproj
__device__ float  g_b1s[AA*NN];     // bias1 * log2 e
__device__ float  g_b2s[NN*AA];     // bias2 * log2 e
__device__ float4 g_qa4[BB*AA];     // pooled Q (avg over segment), w=1
__device__ float4 g_Vagg[BB*HH*AA]; // aggregated V per (b,h,agent), w=1

// ---------------- P1: effective weights + bias scaling + Q pooling ----------------
__global__ void k_pre1(const float* __restrict__ Q,
                       const float* __restrict__ wvel, const float* __restrict__ bvel,
                       const float* __restrict__ winit, const float* __restrict__ binit,
                       const float* __restrict__ wq, const float* __restrict__ bq,
                       const float* __restrict__ wk, const float* __restrict__ bk,
                       const float* __restrict__ wv, const float* __restrict__ bv,
                       const float* __restrict__ bias1, const float* __restrict__ bias2)
{
    int blk = blockIdx.x, tid = threadIdx.x;
    if (blk < 96) {
        // Aq/Ak/Av[i][c] = sum_m L[i][m] * R[m][c]  (i=3 row uses the input bias vector)
        int mat = blk / 32, ctile = blk % 32;
        const float *L, *Lb, *R, *Badd; float* Out;
        if (mat == 0)      { L = wvel;  Lb = bvel;  R = wq; Badd = bq; Out = g_Aq; }
        else if (mat == 1) { L = winit; Lb = binit; R = wk; Badd = bk; Out = g_Ak; }
        else               { L = winit; Lb = binit; R = wv; Badd = bv; Out = g_Av; }
        int cl = tid & 31, mc = tid >> 5;
        int c  = ctile * 32 + cl;
        float a0 = 0.f, a1 = 0.f, a2 = 0.f, a3 = 0.f;
        int m0 = mc * 128;
        #pragma unroll 8
        for (int m = m0; m < m0 + 128; ++m) {
            float r = __ldg(&R[m * 1024 + c]);
            a0 = fmaf(__ldg(&L[m]),        r, a0);
            a1 = fmaf(__ldg(&L[1024 + m]), r, a1);
            a2 = fmaf(__ldg(&L[2048 + m]), r, a2);
            a3 = fmaf(__ldg(&Lb[m]),       r, a3);
        }
        __shared__ float red[8][32][4];
        red[mc][cl][0] = a0; red[mc][cl][1] = a1; red[mc][cl][2] = a2; red[mc][cl][3] = a3;
        __syncthreads();
        if (tid < 32) {
            float s0 = 0.f, s1 = 0.f, s2 = 0.f, s3 = 0.f;
            #pragma unroll
            for (int q = 0; q < 8; ++q) {
                s0 += red[q][tid][0]; s1 += red[q][tid][1];
                s2 += red[q][tid][2]; s3 += red[q][tid][3];
            }
            int cc = ctile * 32 + tid;
            Out[cc]          = s0;
            Out[1024 + cc]   = s1;
            Out[2048 + cc]   = s2;
            Out[3072 + cc]   = s3 + __ldg(&Badd[cc]);
        }
    } else if (blk < 104) {
        // scale bias tensors by log2(e) so softmax uses bare EX2
        int t = (blk - 96) * 256 + tid, stride = 8 * 256;
        for (int i = t; i < AA * NN; i += stride) g_b1s[i] = bias1[i] * LOG2E;
        for (int i = t; i < NN * AA; i += stride) g_b2s[i] = bias2[i] * LOG2E;
    } else {
        // adaptive-avg-pool of Q into 49 agents (3 components + homog. 1)
        int task = (blk - 104) * 256 + tid;
        if (task < BB * AA) {
            int b = task / AA, a = task % AA;
            int s = (a * NN) / AA, e = ((a + 1) * NN + AA - 1) / AA;
            float x = 0.f, y = 0.f, z = 0.f;
            const float* Qb = Q + b * 3072;
            for (int m = s; m < e; ++m) {
                x += __ldg(&Qb[m * 3]);
                y += __ldg(&Qb[m * 3 + 1]);
                z += __ldg(&Qb[m * 3 + 2]);
            }
            float inv = 1.f / (float)(e - s);
            g_qa4[b * AA + a] = make_float4(x * inv, y * inv, z * inv, 1.f);
        }
    }
}

// ---------------- P2: tiny fused tensors (M1, M2, G, T, Db) ----------------
__global__ void k_pre2(const float* __restrict__ wproj, const float* __restrict__ dwcw,
                       const float* __restrict__ dwcb)
{
    int tid = threadIdx.x;
    __shared__ float tpD[36][16];
    __shared__ float tpE[3][16];
    for (int t = tid; t < 704; t += 256) {
        if (t < 512) {
            int isM2 = t >> 8; int t2 = t & 255;
            int h = t2 >> 4, i = (t2 >> 2) & 3, j = t2 & 3;
            const float* X = g_Aq;
            const float* Y = isM2 ? g_Aq : g_Ak;
            float s = 0.f;
            #pragma unroll 8
            for (int d = 0; d < 64; ++d)
                s = fmaf(X[i * 1024 + h * 64 + d], Y[j * 1024 + h * 64 + d], s);
            (isM2 ? g_M2 : g_M1)[h * 16 + i * 4 + j] = s * LOG2E;
        } else {
            int t2 = t - 512;
            int h = t2 / 12, r = t2 % 12, i = r / 3, j = r % 3;
            float s = 0.f;
            #pragma unroll 8
            for (int d = 0; d < 64; ++d) {
                int c = h * 64 + d;
                s = fmaf(g_Av[i * 1024 + c], __ldg(&wproj[c * 3 + j]), s);
            }
            g_G[h * 12 + i * 3 + j] = s;
        }
    }
    for (int t = tid; t < 624; t += 256) {
        if (t < 576) {
            int t36 = t % 36, chunk = t / 36;
            int k = t36 / 9, rr = t36 % 9, tt = rr / 3, j = rr % 3;
            float s = 0.f;
            int c0 = chunk * 64;
            #pragma unroll 4
            for (int c = c0; c < c0 + 64; ++c)
                s = fmaf(g_Av[k * 1024 + c],
                         __ldg(&dwcw[c * 9 + tt * 3 + 1]) * __ldg(&wproj[c * 3 + j]), s);
            tpD[t36][chunk] = s;
        } else {
            int e = t - 576; int j = e % 3, chunk = e / 3;
            float s = 0.f; int c0 = chunk * 64;
            #pragma unroll 4
            for (int c = c0; c < c0 + 64; ++c)
                s = fmaf(__ldg(&dwcb[c]), __ldg(&wproj[c * 3 + j]), s);
            tpE[j][chunk] = s;
        }
    }
    __syncthreads();
    if (tid < 36) { float s = 0.f; for (int q = 0; q < 16; ++q) s += tpD[tid][q]; g_T4[tid] = s; }
    if (tid >= 64 && tid < 67) {
        int j = tid - 64; float s = 0.f;
        for (int q = 0; q < 16; ++q) s += tpE[j][q];
        g_Db[j] = s;
    }
}

// ---------------- S3: agent aggregation (softmax over N, aggregate raw V) ----------------
__global__ void __launch_bounds__(256) k_agg(const float* __restrict__ K, const float* __restrict__ V)
{
    int b = blockIdx.x >> 4, h = blockIdx.x & 15;
    __shared__ float4 k4s[NN];
    __shared__ float4 v4s[NN];
    __shared__ float4 qa4s[AA];
    __shared__ float  M1s[16];
    int tid = threadIdx.x;
    float* kf = (float*)k4s; float* vf = (float*)v4s;
    const float* Kb = K + b * 3072; const float* Vb = V + b * 3072;
    for (int i = tid; i < 3072; i += 256) {
        int n = i / 3, c = i - n * 3;
        kf[n * 4 + c] = __ldg(&Kb[i]);
        vf[n * 4 + c] = __ldg(&Vb[i]);
    }
    for (int n = tid; n < NN; n += 256) { kf[n * 4 + 3] = 1.f; vf[n * 4 + 3] = 0.f; }
    for (int i = tid; i < AA; i += 256) qa4s[i] = g_qa4[b * AA + i];
    if (tid < 16) M1s[tid] = g_M1[h * 16 + tid];
    __syncthreads();

    int warp = tid >> 5, lane = tid & 31;
    for (int a = warp; a < AA; a += 8) {
        float4 qa = qa4s[a];
        float u0 = qa.x * M1s[0] + qa.y * M1s[4] + qa.z * M1s[8]  + M1s[12];
        float u1 = qa.x * M1s[1] + qa.y * M1s[5] + qa.z * M1s[9]  + M1s[13];
        float u2 = qa.x * M1s[2] + qa.y * M1s[6] + qa.z * M1s[10] + M1s[14];
        float u3 = qa.x * M1s[3] + qa.y * M1s[7] + qa.z * M1s[11] + M1s[15];
        const float* brow = &g_b1s[a * NN];
        float s = 0.f, vx = 0.f, vy = 0.f, vz = 0.f;
        #pragma unroll 4
        for (int n = lane; n < NN; n += 32) {
            float4 k4 = k4s[n];
            float l = __ldg(&brow[n]) + u3 + u0 * k4.x + u1 * k4.y + u2 * k4.z;
            float e = fast_exp2(l);
            float4 v = v4s[n];
            s += e;
            vx = fmaf(e, v.x, vx); vy = fmaf(e, v.y, vy); vz = fmaf(e, v.z, vz);
        }
        #pragma unroll
        for (int o = 16; o > 0; o >>= 1) {
            s  += __shfl_xor_sync(0xffffffffu, s,  o);
            vx += __shfl_xor_sync(0xffffffffu, vx, o);
            vy += __shfl_xor_sync(0xffffffffu, vy, o);
            vz += __shfl_xor_sync(0xffffffffu, vz, o);
        }
        if (lane == 0) {
            float inv = __fdividef(1.f, s);
            g_Vagg[(b * 16 + h) * AA + a] = make_float4(vx * inv, vy * inv, vz * inv, 1.f);
        }
    }
}

// ---------------- S4: broadcast attention + conv + projection epilogue ----------------
__global__ void __launch_bounds__(256) k_bc(const float* __restrict__ Q, const float* __restrict__ V,
                                            const float* __restrict__ bproj, float* __restrict__ out)
{
    int b = blockIdx.x >> 3, chunk = blockIdx.x & 7;
    int nbase = chunk * 128;
    __shared__ float  b2sh[128 * AA];
    __shared__ float4 qa4s[AA];
    __shared__ float4 vaggs[HH * AA];
    __shared__ float  M2s[256];
    __shared__ float  Gs[192];
    int tid = threadIdx.x;
    for (int i = tid; i < 128 * AA; i += 256) b2sh[i] = g_b2s[nbase * AA + i];
    for (int i = tid; i < AA; i += 256)       qa4s[i] = g_qa4[b * AA + i];
    for (int i = tid; i < HH * AA; i += 256)  vaggs[i] = g_Vagg[b * HH * AA + i];
    M2s[tid] = g_M2[tid];
    if (tid < 192) Gs[tid] = g_G[tid];
    __syncthreads();

    int nl = tid >> 1, half = tid & 1;
    int n = nbase + nl;
    const float* Qb = Q + b * 3072;
    float q0 = __ldg(&Qb[n * 3]), q1 = __ldg(&Qb[n * 3 + 1]), q2 = __ldg(&Qb[n * 3 + 2]);
    const float* brow = &b2sh[nl * AA];
    float o0 = 0.f, o1 = 0.f, o2 = 0.f;

    for (int hh = 0; hh < 8; ++hh) {
        int h = half * 8 + hh;
        const float* M = &M2s[h * 16];
        float u0 = q0 * M[0] + q1 * M[4] + q2 * M[8]  + M[12];
        float u1 = q0 * M[1] + q1 * M[5] + q2 * M[9]  + M[13];
        float u2 = q0 * M[2] + q1 * M[6] + q2 * M[10] + M[14];
        float u3 = q0 * M[3] + q1 * M[7] + q2 * M[11] + M[15];
        float s = 0.f, ax = 0.f, ay = 0.f, az = 0.f;
        const float4* va = &vaggs[h * AA];
        #pragma unroll 7
        for (int a = 0; a < AA; ++a) {
            float4 qa = qa4s[a];
            float l = brow[a] + u3 + u0 * qa.x + u1 * qa.y + u2 * qa.z;
            float e = fast_exp2(l);
            float4 v = va[a];
            s += e;
            ax = fmaf(e, v.x, ax); ay = fmaf(e, v.y, ay); az = fmaf(e, v.z, az);
        }
        float inv = __fdividef(1.f, s);
        const float* G = &Gs[h * 12];
        o0 += inv * (ax * G[0] + ay * G[3] + az * G[6]) + G[9];
        o1 += inv * (ax * G[1] + ay * G[4] + az * G[7]) + G[10];
        o2 += inv * (ax * G[2] + ay * G[5] + az * G[8]) + G[11];
    }
    o0 += __shfl_xor_sync(0xffffffffu, o0, 1);
    o1 += __shfl_xor_sync(0xffffffffu, o1, 1);
    o2 += __shfl_xor_sync(0xffffffffu, o2, 1);

    if (half == 0) {
        const float* Vb = V + b * 3072;
        float c0 = g_Db[0] + __ldg(&bproj[0]);
        float c1 = g_Db[1] + __ldg(&bproj[1]);
        float c2 = g_Db[2] + __ldg(&bproj[2]);
        #pragma unroll
        for (int t = 0; t < 3; ++t) {
            int m = n + t - 1;
            if (m >= 0 && m < NN) {
                float v0 = __ldg(&Vb[m * 3]), v1 = __ldg(&Vb[m * 3 + 1]), v2 = __ldg(&Vb[m * 3 + 2]);
                c0 += v0 * g_T4[0 * 9 + t * 3 + 0] + v1 * g_T4[1 * 9 + t * 3 + 0]
                    + v2 * g_T4[2 * 9 + t * 3 + 0] + g_T4[3 * 9 + t * 3 + 0];
                c1 += v0 * g_T4[0 * 9 + t * 3 + 1] + v1 * g_T4[1 * 9 + t * 3 + 1]
                    + v2 * g_T4[2 * 9 + t * 3 + 1] + g_T4[3 * 9 + t * 3 + 1];
                c2 += v0 * g_T4[0 * 9 + t * 3 + 2] + v1 * g_T4[1 * 9 + t * 3 + 2]
                    + v2 * g_T4[2 * 9 + t * 3 + 2] + g_T4[3 * 9 + t * 3 + 2];
            }
        }
        out[b * 3072 + n]        = o0 + c0;
        out[b * 3072 + 1024 + n] = o1 + c1;
        out[b * 3072 + 2048 + n] = o2 + c2;
    }
}

// ---------------- launch ----------------
extern "C" void kernel_launch(void* const* d_in, const int* in_sizes, int n_in,
                              void* d_out, int out_size)
{
    const float* Q     = (const float*)d_in[0];
    const float* K     = (const float*)d_in[1];
    const float* V     = (const float*)d_in[2];
    const float* wvel  = (const float*)d_in[3];
    const float* bvel  = (const float*)d_in[4];
    const float* winit = (const float*)d_in[5];
    const float* binit = (const float*)d_in[6];
    const float* wq    = (const float*)d_in[7];
    const float* bq    = (const float*)d_in[8];
    const float* wk    = (const float*)d_in[9];
    const float* bk    = (const float*)d_in[10];
    const float* wv    = (const float*)d_in[11];
    const float* bv    = (const float*)d_in[12];
    const float* b1    = (const float*)d_in[13];
    const float* b2    = (const float*)d_in[14];
    const float* dwcw  = (const float*)d_in[15];
    const float* dwcb  = (const float*)d_in[16];
    const float* wproj = (const float*)d_in[17];
    const float* bproj = (const float*)d_in[18];
    float* out = (float*)d_out;

    k_pre1<<<111, 256>>>(Q, wvel, bvel, winit, binit, wq, bq, wk, bk, wv, bv, b1, b2);
    k_pre2<<<1, 256>>>(wproj, dwcw, dwcb);
    k_agg<<<512, 256>>>(K, V);
    k_bc<<<256, 256>>>(Q, V, bproj, out);
}